// round 3
// baseline (speedup 1.0000x reference)
#include <cuda_runtime.h>
#include <cuda_bf16.h>
#include <math.h>

typedef unsigned long long ull;

#define ENT   20000
#define RELN  500
#define DIM   64
#define TSZ   256
#define BM    64
#define BN    128

// Scratch (device globals — no allocation allowed)
__device__ float g_hr[TSZ * DIM];   // hr = ent[h] + rel[r]
__device__ float g_nh[TSZ];         // ||hr||^2
__device__ float g_ne[ENT];         // ||ent[j]||^2

__device__ __forceinline__ ull pack2(float x, float y) {
    ull u;
    asm("mov.b64 %0, {%1, %2};" : "=l"(u) : "f"(x), "f"(y));
    return u;
}
__device__ __forceinline__ void unpack2(ull u, float& x, float& y) {
    asm("mov.b64 {%0, %1}, %2;" : "=f"(x), "=f"(y) : "l"(u));
}
__device__ __forceinline__ void fma2(ull& acc, ull a, ull b) {
    asm("fma.rn.f32x2 %0, %1, %2, %0;" : "+l"(acc) : "l"(a), "l"(b));
}

// ---------------------------------------------------------------------------
// prep_hr: hr[i] = ent_emb[h[i]] + rel_emb[r[i]],  nh[i] = ||hr[i]||^2
// NOTE: h/r are int32 (JAX x64-disabled downcasts jnp.int64 -> int32).
// ---------------------------------------------------------------------------
__global__ void prep_hr_kernel(const float* __restrict__ ent,
                               const float* __restrict__ rel,
                               const int* __restrict__ h,
                               const int* __restrict__ r) {
    int i = blockIdx.x * blockDim.x + threadIdx.x;
    if (i >= TSZ) return;
    int hi = h[i];
    int ri = r[i];
    const float4* eh = (const float4*)(ent + (size_t)hi * DIM);
    const float4* rr = (const float4*)(rel + (size_t)ri * DIM);
    float4* dst = (float4*)(g_hr + i * DIM);
    float s = 0.0f;
#pragma unroll
    for (int k = 0; k < DIM / 4; k++) {
        float4 a = eh[k], b = rr[k];
        float4 v = make_float4(a.x + b.x, a.y + b.y, a.z + b.z, a.w + b.w);
        dst[k] = v;
        s += v.x * v.x + v.y * v.y + v.z * v.z + v.w * v.w;
    }
    g_nh[i] = s;
}

// ---------------------------------------------------------------------------
// prep_ne: ne[j] = ||ent_emb[j]||^2
// ---------------------------------------------------------------------------
__global__ void prep_ne_kernel(const float* __restrict__ ent) {
    int j = blockIdx.x * blockDim.x + threadIdx.x;
    if (j >= ENT) return;
    const float4* e = (const float4*)(ent + (size_t)j * DIM);
    float s = 0.0f;
#pragma unroll
    for (int k = 0; k < DIM / 4; k++) {
        float4 v = e[k];
        s += v.x * v.x + v.y * v.y + v.z * v.z + v.w * v.w;
    }
    g_ne[j] = s;
}

// ---------------------------------------------------------------------------
// Main: score[i][j] = sqrt(nh[i] + ne[j] - 2 * dot(hr[i], ent[j]))
// GEMM tile BM x BN, K=64 packed as 32 f32x2 steps. fma.rn.f32x2 throughout.
// ---------------------------------------------------------------------------
__global__ void __launch_bounds__(256, 2)
transe_score_kernel(const float* __restrict__ ent, float* __restrict__ out) {
    __shared__ float sA[BM * DIM];          // 16 KB: hr tile, row-major
    __shared__ ull   sB2[32 * BN];          // 32 KB: ent tile, [kpair][j] float2, XOR-swizzled

    const int tid = threadIdx.x;
    const int jT  = blockIdx.x * BN;
    const int iT  = blockIdx.y * BM;

    // --- load HR tile (64 rows x 64 floats) ---
#pragma unroll
    for (int it = 0; it < 4; it++) {
        int idx = tid + it * 256;           // 1024 float4 items
        int i   = idx >> 4;
        int k4  = idx & 15;
        float4 v = *(const float4*)(g_hr + (size_t)(iT + i) * DIM + k4 * 4);
        *(float4*)(sA + i * DIM + k4 * 4) = v;
    }

    // --- load ENT tile (128 rows x 64 floats) into [kpair][j] swizzled planes ---
#pragma unroll
    for (int it = 0; it < 8; it++) {
        int idx = tid + it * 256;           // 2048 float4 items
        int j   = idx >> 4;
        int k4  = idx & 15;
        int jG  = jT + j;
        float4 v = make_float4(0.f, 0.f, 0.f, 0.f);
        if (jG < ENT) v = *(const float4*)(ent + (size_t)jG * DIM + k4 * 4);
        int js = j ^ (k4 & 15);             // bank swizzle
        sB2[(2 * k4)     * BN + js] = pack2(v.x, v.y);
        sB2[(2 * k4 + 1) * BN + js] = pack2(v.z, v.w);
    }
    __syncthreads();

    const int tx = tid & 31;
    const int ty = tid >> 5;
    const int iBase = ty * 8;               // 8 rows per thread

    ull acc[8][4];
#pragma unroll
    for (int ii = 0; ii < 8; ii++)
#pragma unroll
        for (int jj = 0; jj < 4; jj++) acc[ii][jj] = pack2(0.0f, 0.0f);

#pragma unroll 4
    for (int kk = 0; kk < 32; kk++) {
        ull a2[8], b2[4];
        const int s = (kk >> 1) & 15;
#pragma unroll
        for (int ii = 0; ii < 8; ii++)
            a2[ii] = *(const ull*)(sA + (iBase + ii) * DIM + kk * 2);   // broadcast
#pragma unroll
        for (int jj = 0; jj < 4; jj++)
            b2[jj] = sB2[kk * BN + ((tx + 32 * jj) ^ s)];               // conflict-free
#pragma unroll
        for (int ii = 0; ii < 8; ii++)
#pragma unroll
            for (int jj = 0; jj < 4; jj++)
                fma2(acc[ii][jj], a2[ii], b2[jj]);
    }

    // --- epilogue: score = sqrt(nh + ne - 2*dot) ---
#pragma unroll
    for (int ii = 0; ii < 8; ii++) {
        int iG = iT + iBase + ii;
        float nh = g_nh[iG];
#pragma unroll
        for (int jj = 0; jj < 4; jj++) {
            int jG = jT + tx + 32 * jj;
            if (jG < ENT) {
                float lo, hi;
                unpack2(acc[ii][jj], lo, hi);
                float d2 = nh + g_ne[jG] - 2.0f * (lo + hi);
                out[(size_t)iG * ENT + jG] = sqrtf(fmaxf(d2, 0.0f));
            }
        }
    }
}

// ---------------------------------------------------------------------------
// Inputs (metadata order): ent_emb f32[20000*64], rel_emb f32[500*64],
//                          h i32[256], r i32[256], t i32[256], (batch_size)
// Output: f32[256*20000]  (pos rows 0..127, neg rows 128..255, contiguous)
// ---------------------------------------------------------------------------
extern "C" void kernel_launch(void* const* d_in, const int* in_sizes, int n_in,
                              void* d_out, int out_size) {
    const float* ent = (const float*)d_in[0];
    const float* rel = (const float*)d_in[1];
    const int*   h   = (const int*)d_in[2];
    const int*   r   = (const int*)d_in[3];
    float*       out = (float*)d_out;

    prep_hr_kernel<<<1, 256>>>(ent, rel, h, r);
    prep_ne_kernel<<<(ENT + 255) / 256, 256>>>(ent);

    dim3 grid((ENT + BN - 1) / BN, TSZ / BM);   // 157 x 4
    transe_score_kernel<<<grid, 256>>>(ent, out);
}

// round 5
// speedup vs baseline: 1.2645x; 1.2645x over previous
#include <cuda_runtime.h>
#include <cuda_bf16.h>
#include <math.h>

typedef unsigned long long ull;

#define ENT   20000
#define RELN  500
#define DIM   64
#define TSZ   256
#define BM    64
#define BN    128

// Scratch (device globals — no allocation allowed)
__device__ float g_hr[TSZ * DIM];   // hr = ent[h] + rel[r]
__device__ float g_nh[TSZ];         // ||hr||^2
__device__ float g_ne[ENT];         // ||ent[j]||^2

__device__ __forceinline__ ull pack2(float x, float y) {
    ull u;
    asm("mov.b64 %0, {%1, %2};" : "=l"(u) : "f"(x), "f"(y));
    return u;
}
__device__ __forceinline__ void unpack2(ull u, float& x, float& y) {
    asm("mov.b64 {%0, %1}, %2;" : "=f"(x), "=f"(y) : "l"(u));
}
__device__ __forceinline__ void fma2(ull& acc, ull a, ull b) {
    asm("fma.rn.f32x2 %0, %1, %2, %0;" : "+l"(acc) : "l"(a), "l"(b));
}

// ---------------------------------------------------------------------------
// prep: blocks [0,79) compute ne[j] = ||ent[j]||^2  (j = b*256 + tid)
//       blocks [79,95) compute hr rows with 16 threads/row (low latency)
// ---------------------------------------------------------------------------
__global__ void __launch_bounds__(256)
prep_kernel(const float* __restrict__ ent,
            const float* __restrict__ rel,
            const int* __restrict__ h,
            const int* __restrict__ r) {
    const int b   = blockIdx.x;
    const int tid = threadIdx.x;

    if (b < 79) {
        int j = b * 256 + tid;
        if (j < ENT) {
            const float4* e = (const float4*)(ent + (size_t)j * DIM);
            float s = 0.0f;
#pragma unroll
            for (int k = 0; k < DIM / 4; k++) {
                float4 v = e[k];
                s += v.x * v.x + v.y * v.y + v.z * v.z + v.w * v.w;
            }
            g_ne[j] = s;
        }
    } else {
        // hr: 16 rows per block, 16 threads per row, 1 float4 per thread
        int hb  = b - 79;                    // 0..15
        int row = hb * 16 + (tid >> 4);      // 0..255
        int k4  = tid & 15;
        int hi = h[row];
        int ri = r[row];
        float4 a = *(const float4*)(ent + (size_t)hi * DIM + k4 * 4);
        float4 c = *(const float4*)(rel + (size_t)ri * DIM + k4 * 4);
        float4 v = make_float4(a.x + c.x, a.y + c.y, a.z + c.z, a.w + c.w);
        *(float4*)(g_hr + (size_t)row * DIM + k4 * 4) = v;
        float s = v.x * v.x + v.y * v.y + v.z * v.z + v.w * v.w;
#pragma unroll
        for (int o = 8; o >= 1; o >>= 1)
            s += __shfl_xor_sync(0xffffffffu, s, o, 16);
        if (k4 == 0) g_nh[row] = s;
    }
}

// ---------------------------------------------------------------------------
// Main: score[i][j] = sqrt(nh[i] + ne[j] - 2 * dot(hr[i], ent[j]))
// GEMM tile BM x BN. sB laid out as [k4][j] float4 planes (XOR-swizzled) so
// the inner loop is 16 k4-steps of LDS.128 + 2x fma.rn.f32x2 per (ii,jj).
// ---------------------------------------------------------------------------
__global__ void __launch_bounds__(256, 2)
transe_score_kernel(const float* __restrict__ ent, float* __restrict__ out) {
    __shared__ float sA[BM * DIM];              // 16 KB: hr tile, row-major
    __shared__ float4 sB4[16 * BN];             // 32 KB: ent tile [k4][j] swizzled

    const int tid = threadIdx.x;
    const int jT  = blockIdx.x * BN;
    const int iT  = blockIdx.y * BM;

    // --- load HR tile (64 rows x 64 floats) ---
#pragma unroll
    for (int it = 0; it < 4; it++) {
        int idx = tid + it * 256;               // 1024 float4 items
        int i   = idx >> 4;
        int k4  = idx & 15;
        float4 v = *(const float4*)(g_hr + (size_t)(iT + i) * DIM + k4 * 4);
        *(float4*)(sA + i * DIM + k4 * 4) = v;
    }

    // --- load ENT tile (128 rows x 64 floats) into [k4][j] swizzled planes ---
#pragma unroll
    for (int it = 0; it < 8; it++) {
        int idx = tid + it * 256;               // 2048 float4 items
        int j   = idx >> 4;
        int k4  = idx & 15;
        int jG  = jT + j;
        float4 v = make_float4(0.f, 0.f, 0.f, 0.f);
        if (jG < ENT) v = *(const float4*)(ent + (size_t)jG * DIM + k4 * 4);
        sB4[k4 * BN + (j ^ k4)] = v;            // bank swizzle vs k4
    }
    __syncthreads();

    const int tx = tid & 31;
    const int ty = tid >> 5;
    const int iBase = ty * 8;                   // 8 rows per thread

    ull acc[8][4];
#pragma unroll
    for (int ii = 0; ii < 8; ii++)
#pragma unroll
        for (int jj = 0; jj < 4; jj++) acc[ii][jj] = pack2(0.0f, 0.0f);

#pragma unroll 4
    for (int k4 = 0; k4 < 16; k4++) {
        ulonglong2 a4[8], b4[4];
#pragma unroll
        for (int ii = 0; ii < 8; ii++)          // broadcast LDS.128
            a4[ii] = *(const ulonglong2*)(sA + (iBase + ii) * DIM + k4 * 4);
#pragma unroll
        for (int jj = 0; jj < 4; jj++)          // conflict-free LDS.128
            b4[jj] = *(const ulonglong2*)(&sB4[k4 * BN + ((tx + 32 * jj) ^ k4)]);
#pragma unroll
        for (int ii = 0; ii < 8; ii++)
#pragma unroll
            for (int jj = 0; jj < 4; jj++) {
                fma2(acc[ii][jj], a4[ii].x, b4[jj].x);
                fma2(acc[ii][jj], a4[ii].y, b4[jj].y);
            }
    }

    // --- epilogue: score = sqrt(nh + ne - 2*dot) ---
#pragma unroll
    for (int ii = 0; ii < 8; ii++) {
        int iG = iT + iBase + ii;
        float nh = g_nh[iG];
#pragma unroll
        for (int jj = 0; jj < 4; jj++) {
            int jG = jT + tx + 32 * jj;
            if (jG < ENT) {
                float lo, hi;
                unpack2(acc[ii][jj], lo, hi);
                float d2 = nh + g_ne[jG] - 2.0f * (lo + hi);
                out[(size_t)iG * ENT + jG] = sqrtf(fmaxf(d2, 0.0f));
            }
        }
    }
}

// ---------------------------------------------------------------------------
// Inputs (metadata order): ent_emb f32[20000*64], rel_emb f32[500*64],
//                          h i32[256], r i32[256], t i32[256], (batch_size)
// Output: f32[256*20000]  (pos rows 0..127, neg rows 128..255, contiguous)
// ---------------------------------------------------------------------------
extern "C" void kernel_launch(void* const* d_in, const int* in_sizes, int n_in,
                              void* d_out, int out_size) {
    const float* ent = (const float*)d_in[0];
    const float* rel = (const float*)d_in[1];
    const int*   h   = (const int*)d_in[2];
    const int*   r   = (const int*)d_in[3];
    float*       out = (float*)d_out;

    prep_kernel<<<95, 256>>>(ent, rel, h, r);

    dim3 grid((ENT + BN - 1) / BN, TSZ / BM);   // 157 x 4
    transe_score_kernel<<<grid, 256>>>(ent, out);
}

// round 7
// speedup vs baseline: 2.2075x; 1.7457x over previous
#include <cuda_runtime.h>
#include <cstdint>
#include <math.h>

#define ENT   20000
#define RELN  500
#define DIM   64
#define TSZ   256
#define BM    128
#define BN    128
#define PA    68          // smem pitch in floats (bank-bijective fragments)

// SMEM float offsets
#define OFF_A   0
#define OFF_B   (128 * PA)            // 8704
#define OFF_NH  (2 * 128 * PA)        // 17408
#define OFF_NE  (2 * 128 * PA + 128)  // 17536
#define SM_FLOATS (2 * 128 * PA + 256)
#define SM_BYTES  (SM_FLOATS * 4)     // 70656

__device__ __forceinline__ uint32_t f2tf32(float x) {
    uint32_t u;
    asm("cvt.rna.tf32.f32 %0, %1;" : "=r"(u) : "f"(x));
    return u;
}
__device__ __forceinline__ float sqrt_approx(float x) {
    float y;
    asm("sqrt.approx.f32 %0, %1;" : "=f"(y) : "f"(x));
    return y;
}
__device__ __forceinline__ void mma_tf32(float* d, const uint32_t* a,
                                         uint32_t b0, uint32_t b1) {
    asm volatile(
        "mma.sync.aligned.m16n8k8.row.col.f32.tf32.tf32.f32 "
        "{%0,%1,%2,%3}, {%4,%5,%6,%7}, {%8,%9}, {%0,%1,%2,%3};"
        : "+f"(d[0]), "+f"(d[1]), "+f"(d[2]), "+f"(d[3])
        : "r"(a[0]), "r"(a[1]), "r"(a[2]), "r"(a[3]), "r"(b0), "r"(b1));
}

// ---------------------------------------------------------------------------
// score[i][j] = sqrt(||hr_i||^2 + ||ent_j||^2 - 2 * dot(hr_i, ent_j))
// Cross term via legacy tf32 warp MMA (m16n8k8), norms fused in tile load.
// ---------------------------------------------------------------------------
__global__ void __launch_bounds__(256, 2)
transe_mma_kernel(const float* __restrict__ ent, const float* __restrict__ rel,
                  const int* __restrict__ h, const int* __restrict__ r,
                  float* __restrict__ out) {
    extern __shared__ float sm[];
    float* sA  = sm + OFF_A;      // [128][PA] tf32 bits of hr
    float* sB  = sm + OFF_B;      // [128][PA] tf32 bits of ent tile
    float* sNH = sm + OFF_NH;     // [128]
    float* sNE = sm + OFF_NE;     // [128]

    const int tid  = threadIdx.x;
    const int lane = tid & 31;
    const int warp = tid >> 5;
    const int jT   = blockIdx.x * BN;
    const int iT   = blockIdx.y * BM;

    // ---- load B tile (ent rows jT..jT+127) + ne, tf32-converted ----
#pragma unroll
    for (int it = 0; it < 8; it++) {
        int idx = it * 256 + tid;       // 2048 float4
        int row = idx >> 4;
        int q   = idx & 15;
        int jG  = jT + row;
        float4 v = make_float4(0.f, 0.f, 0.f, 0.f);
        if (jG < ENT) v = *(const float4*)(ent + (size_t)jG * DIM + q * 4);
        float s = v.x * v.x + v.y * v.y + v.z * v.z + v.w * v.w;
#pragma unroll
        for (int o = 8; o >= 1; o >>= 1) s += __shfl_xor_sync(0xffffffffu, s, o, 16);
        if (q == 0) sNE[row] = s;
        uint32_t* dst = (uint32_t*)(sB + row * PA + q * 4);
        dst[0] = f2tf32(v.x); dst[1] = f2tf32(v.y);
        dst[2] = f2tf32(v.z); dst[3] = f2tf32(v.w);
    }
    // ---- load A tile: hr = ent[h]+rel[r] rows iT..iT+127, + nh ----
#pragma unroll
    for (int it = 0; it < 8; it++) {
        int idx = it * 256 + tid;
        int row = idx >> 4;
        int q   = idx & 15;
        int hI  = h[iT + row];
        int rI  = r[iT + row];
        float4 a = *(const float4*)(ent + (size_t)hI * DIM + q * 4);
        float4 c = *(const float4*)(rel + (size_t)rI * DIM + q * 4);
        float4 v = make_float4(a.x + c.x, a.y + c.y, a.z + c.z, a.w + c.w);
        float s = v.x * v.x + v.y * v.y + v.z * v.z + v.w * v.w;
#pragma unroll
        for (int o = 8; o >= 1; o >>= 1) s += __shfl_xor_sync(0xffffffffu, s, o, 16);
        if (q == 0) sNH[row] = s;
        uint32_t* dst = (uint32_t*)(sA + row * PA + q * 4);
        dst[0] = f2tf32(v.x); dst[1] = f2tf32(v.y);
        dst[2] = f2tf32(v.z); dst[3] = f2tf32(v.w);
    }
    __syncthreads();

    // ---- mainloop: warp (wm, wn) owns rows wm*32+[0,32), cols wn*64+[0,64) ----
    const int wm  = warp & 3;
    const int wn  = warp >> 2;
    const int grp = lane >> 2;      // 0..7
    const int t4  = lane & 3;       // 0..3

    float d[2][8][4];
#pragma unroll
    for (int f = 0; f < 2; f++)
#pragma unroll
        for (int g = 0; g < 8; g++)
#pragma unroll
            for (int e = 0; e < 4; e++) d[f][g][e] = 0.0f;

    const uint32_t* uA = (const uint32_t*)sA;
    const uint32_t* uB = (const uint32_t*)sB;
    const int aR = (wm * 32 + grp) * PA;
    const int bR = (wn * 64 + grp) * PA;

#pragma unroll
    for (int ch = 0; ch < 8; ch++) {
        const int kb = ch * 8 + t4;
        uint32_t a[2][4];
#pragma unroll
        for (int f = 0; f < 2; f++) {
            int base = aR + f * 16 * PA;
            a[f][0] = uA[base + kb];
            a[f][1] = uA[base + 8 * PA + kb];
            a[f][2] = uA[base + kb + 4];
            a[f][3] = uA[base + 8 * PA + kb + 4];
        }
#pragma unroll
        for (int g = 0; g < 8; g++) {
            uint32_t b0 = uB[bR + g * 8 * PA + kb];
            uint32_t b1 = uB[bR + g * 8 * PA + kb + 4];
            mma_tf32(d[0][g], a[0], b0, b1);
            mma_tf32(d[1][g], a[1], b0, b1);
        }
    }

    // ---- epilogue: c0/c1 at (row, 2*t4 / +1); c2/c3 at row+8 ----
#pragma unroll
    for (int f = 0; f < 2; f++) {
        int rl0 = wm * 32 + f * 16 + grp;
        int rl1 = rl0 + 8;
        float nh0 = sNH[rl0];
        float nh1 = sNH[rl1];
        size_t ob0 = (size_t)(iT + rl0) * ENT;
        size_t ob1 = (size_t)(iT + rl1) * ENT;
#pragma unroll
        for (int g = 0; g < 8; g++) {
            int cl = wn * 64 + g * 8 + t4 * 2;
            int jG = jT + cl;
            if (jG < ENT) {
                float2 ne2 = *(const float2*)(sNE + cl);
                float2 s0, s1;
                s0.x = sqrt_approx(fmaxf(nh0 + ne2.x - 2.0f * d[f][g][0], 0.0f));
                s0.y = sqrt_approx(fmaxf(nh0 + ne2.y - 2.0f * d[f][g][1], 0.0f));
                s1.x = sqrt_approx(fmaxf(nh1 + ne2.x - 2.0f * d[f][g][2], 0.0f));
                s1.y = sqrt_approx(fmaxf(nh1 + ne2.y - 2.0f * d[f][g][3], 0.0f));
                *(float2*)(out + ob0 + jG) = s0;
                *(float2*)(out + ob1 + jG) = s1;
            }
        }
    }
}

// ---------------------------------------------------------------------------
// Inputs (metadata order): ent_emb f32[20000*64], rel_emb f32[500*64],
//                          h i32[256], r i32[256], t i32[256], (batch_size)
// Output: f32[256*20000]
// ---------------------------------------------------------------------------
extern "C" void kernel_launch(void* const* d_in, const int* in_sizes, int n_in,
                              void* d_out, int out_size) {
    const float* ent = (const float*)d_in[0];
    const float* rel = (const float*)d_in[1];
    const int*   h   = (const int*)d_in[2];
    const int*   r   = (const int*)d_in[3];
    float*       out = (float*)d_out;

    cudaFuncSetAttribute(transe_mma_kernel,
                         cudaFuncAttributeMaxDynamicSharedMemorySize, SM_BYTES);

    dim3 grid((ENT + BN - 1) / BN, TSZ / BM);   // 157 x 2
    transe_mma_kernel<<<grid, 256, SM_BYTES>>>(ent, rel, h, r, out);
}

// round 8
// speedup vs baseline: 2.3083x; 1.0457x over previous
#include <cuda_runtime.h>
#include <cstdint>
#include <math.h>

#define ENT   20000
#define RELN  500
#define DIM   64
#define TSZ   256
#define BM    256
#define BN    128
#define NCT   157         // ceil(20000/128) column tiles
#define GRID  148         // one CTA per SM, persistent over column tiles
#define PA    68          // smem pitch in floats (bank-bijective fragments)

// SMEM float offsets
#define OFF_A   0
#define OFF_B   (BM * PA)                  // 17408
#define OFF_NH  (BM * PA + BN * PA)        // 26112
#define OFF_NE  (OFF_NH + BM)              // 26368
#define SM_FLOATS (OFF_NE + BN)            // 26496
#define SM_BYTES  (SM_FLOATS * 4)          // 105984

__device__ __forceinline__ float sqrt_approx(float x) {
    float y;
    asm("sqrt.approx.f32 %0, %1;" : "=f"(y) : "f"(x));
    return y;
}
__device__ __forceinline__ void mma_tf32(float* d, const uint32_t* a,
                                         uint32_t b0, uint32_t b1) {
    asm volatile(
        "mma.sync.aligned.m16n8k8.row.col.f32.tf32.tf32.f32 "
        "{%0,%1,%2,%3}, {%4,%5,%6,%7}, {%8,%9}, {%0,%1,%2,%3};"
        : "+f"(d[0]), "+f"(d[1]), "+f"(d[2]), "+f"(d[3])
        : "r"(a[0]), "r"(a[1]), "r"(a[2]), "r"(a[3]), "r"(b0), "r"(b1));
}

// ---------------------------------------------------------------------------
// score[i][j] = sqrt(||hr_i||^2 + ||ent_j||^2 - 2 * dot(hr_i, ent_j))
// One persistent CTA per SM; A (all 256 hr rows) loaded once, then loop over
// column tiles. tf32 MMA on raw f32 bits (HW truncation).
// ---------------------------------------------------------------------------
__global__ void __launch_bounds__(512, 1)
transe_mma_kernel(const float* __restrict__ ent, const float* __restrict__ rel,
                  const int* __restrict__ h, const int* __restrict__ r,
                  float* __restrict__ out) {
    extern __shared__ float sm[];
    float* sA  = sm + OFF_A;      // [256][PA] hr (raw f32)
    float* sB  = sm + OFF_B;      // [128][PA] ent tile (raw f32)
    float* sNH = sm + OFF_NH;     // [256]
    float* sNE = sm + OFF_NE;     // [128]

    const int tid  = threadIdx.x;
    const int lane = tid & 31;
    const int warp = tid >> 5;

    // ---- load A tile once: hr = ent[h]+rel[r], all 256 rows, + nh ----
#pragma unroll
    for (int it = 0; it < 8; it++) {
        int idx = it * 512 + tid;       // 4096 float4 slots
        int row = idx >> 4;
        int q   = idx & 15;
        int hI  = h[row];
        int rI  = r[row];
        float4 a = *(const float4*)(ent + (size_t)hI * DIM + q * 4);
        float4 c = *(const float4*)(rel + (size_t)rI * DIM + q * 4);
        float4 v = make_float4(a.x + c.x, a.y + c.y, a.z + c.z, a.w + c.w);
        float s = v.x * v.x + v.y * v.y + v.z * v.z + v.w * v.w;
#pragma unroll
        for (int o = 8; o >= 1; o >>= 1) s += __shfl_xor_sync(0xffffffffu, s, o, 16);
        if (q == 0) sNH[row] = s;
        *(float4*)(sA + row * PA + q * 4) = v;
    }

    const int wm  = warp >> 1;      // 0..7  (row block of 32)
    const int wn  = warp & 1;       // 0..1  (col block of 64)
    const int grp = lane >> 2;      // 0..7
    const int t4  = lane & 3;       // 0..3

    const uint32_t* uA = (const uint32_t*)sA;
    const uint32_t* uB = (const uint32_t*)sB;
    const int aR = (wm * 32 + grp) * PA;
    const int bR0 = (wn * 64 + grp) * PA;

    // ---- persistent loop over column tiles ----
    for (int ct = blockIdx.x; ct < NCT; ct += GRID) {
        const int jT = ct * BN;
        __syncthreads();            // A ready (1st) / prev iter done with sB,sNE

        // load B tile (ent rows jT..jT+127) + ne
#pragma unroll
        for (int it = 0; it < 4; it++) {
            int idx = it * 512 + tid;   // 2048 float4 slots
            int row = idx >> 4;
            int q   = idx & 15;
            int jG  = jT + row;
            float4 v = make_float4(0.f, 0.f, 0.f, 0.f);
            if (jG < ENT) v = *(const float4*)(ent + (size_t)jG * DIM + q * 4);
            float s = v.x * v.x + v.y * v.y + v.z * v.z + v.w * v.w;
#pragma unroll
            for (int o = 8; o >= 1; o >>= 1) s += __shfl_xor_sync(0xffffffffu, s, o, 16);
            if (q == 0) sNE[row] = s;
            *(float4*)(sB + row * PA + q * 4) = v;
        }
        __syncthreads();

        // mainloop: warp tile 32x64, 8 k-chunks of 8
        float d[2][8][4];
#pragma unroll
        for (int f = 0; f < 2; f++)
#pragma unroll
            for (int g = 0; g < 8; g++)
#pragma unroll
                for (int e = 0; e < 4; e++) d[f][g][e] = 0.0f;

#pragma unroll
        for (int ch = 0; ch < 8; ch++) {
            const int kb = ch * 8 + t4;
            uint32_t a[2][4];
#pragma unroll
            for (int f = 0; f < 2; f++) {
                int base = aR + f * 16 * PA;
                a[f][0] = uA[base + kb];
                a[f][1] = uA[base + 8 * PA + kb];
                a[f][2] = uA[base + kb + 4];
                a[f][3] = uA[base + 8 * PA + kb + 4];
            }
#pragma unroll
            for (int g = 0; g < 8; g++) {
                uint32_t b0 = uB[bR0 + g * 8 * PA + kb];
                uint32_t b1 = uB[bR0 + g * 8 * PA + kb + 4];
                mma_tf32(d[0][g], a[0], b0, b1);
                mma_tf32(d[1][g], a[1], b0, b1);
            }
        }

        // epilogue
#pragma unroll
        for (int f = 0; f < 2; f++) {
            int rl0 = wm * 32 + f * 16 + grp;
            int rl1 = rl0 + 8;
            float nh0 = sNH[rl0];
            float nh1 = sNH[rl1];
            float* o0 = out + (size_t)rl0 * ENT + jT;
            float* o1 = out + (size_t)rl1 * ENT + jT;
#pragma unroll
            for (int g = 0; g < 8; g++) {
                int cl = wn * 64 + g * 8 + t4 * 2;
                if (jT + cl < ENT) {
                    float2 ne2 = *(const float2*)(sNE + cl);
                    float2 s0, s1;
                    s0.x = sqrt_approx(fmaxf(nh0 + ne2.x - 2.0f * d[f][g][0], 0.0f));
                    s0.y = sqrt_approx(fmaxf(nh0 + ne2.y - 2.0f * d[f][g][1], 0.0f));
                    s1.x = sqrt_approx(fmaxf(nh1 + ne2.x - 2.0f * d[f][g][2], 0.0f));
                    s1.y = sqrt_approx(fmaxf(nh1 + ne2.y - 2.0f * d[f][g][3], 0.0f));
                    *(float2*)(o0 + cl) = s0;
                    *(float2*)(o1 + cl) = s1;
                }
            }
        }
    }
}

// ---------------------------------------------------------------------------
// Inputs (metadata order): ent_emb f32[20000*64], rel_emb f32[500*64],
//                          h i32[256], r i32[256], t i32[256], (batch_size)
// Output: f32[256*20000]
// ---------------------------------------------------------------------------
extern "C" void kernel_launch(void* const* d_in, const int* in_sizes, int n_in,
                              void* d_out, int out_size) {
    const float* ent = (const float*)d_in[0];
    const float* rel = (const float*)d_in[1];
    const int*   h   = (const int*)d_in[2];
    const int*   r   = (const int*)d_in[3];
    float*       out = (float*)d_out;

    cudaFuncSetAttribute(transe_mma_kernel,
                         cudaFuncAttributeMaxDynamicSharedMemorySize, SM_BYTES);

    transe_mma_kernel<<<GRID, 512, SM_BYTES>>>(ent, rel, h, r, out);
}

// round 9
// speedup vs baseline: 3.1099x; 1.3473x over previous
#include <cuda_runtime.h>
#include <cstdint>
#include <math.h>

#define ENT   20000
#define RELN  500
#define DIM   64
#define TSZ   256
#define BM    128
#define BN    144         // 18 n8-tiles; 139 col tiles cover 20016 >= 20000
#define NCT   139
#define PA    68          // smem pitch in floats (bank-bijective fragments)

// SMEM float offsets
#define OFF_A   0
#define OFF_B   (BM * PA)                  // 8704
#define OFF_NH  (OFF_B + BN * PA)          // 18496
#define OFF_NE  (OFF_NH + BM)              // 18624
#define SM_FLOATS (OFF_NE + BN)            // 18768
#define SM_BYTES  (SM_FLOATS * 4)          // 75072

__device__ __forceinline__ float sqrt_approx(float x) {
    float y;
    asm("sqrt.approx.f32 %0, %1;" : "=f"(y) : "f"(x));
    return y;
}
__device__ __forceinline__ void mma_tf32(float* d, const uint32_t* a,
                                         uint32_t b0, uint32_t b1) {
    asm volatile(
        "mma.sync.aligned.m16n8k8.row.col.f32.tf32.tf32.f32 "
        "{%0,%1,%2,%3}, {%4,%5,%6,%7}, {%8,%9}, {%0,%1,%2,%3};"
        : "+f"(d[0]), "+f"(d[1]), "+f"(d[2]), "+f"(d[3])
        : "r"(a[0]), "r"(a[1]), "r"(a[2]), "r"(a[3]), "r"(b0), "r"(b1));
}

// ---------------------------------------------------------------------------
// score[i][j] = sqrt(||hr_i||^2 + ||ent_j||^2 - 2 * dot(hr_i, ent_j))
// One tile (128 rows x 144 cols) per CTA; 278 CTAs, 2 resident per SM.
// A+B loads fused into one phase (single barrier). tf32 MMA on raw f32 bits.
// ---------------------------------------------------------------------------
__global__ void __launch_bounds__(256, 2)
transe_mma_kernel(const float* __restrict__ ent, const float* __restrict__ rel,
                  const int* __restrict__ h, const int* __restrict__ r,
                  float* __restrict__ out) {
    extern __shared__ float sm[];
    float* sA  = sm + OFF_A;      // [128][PA] hr (raw f32)
    float* sB  = sm + OFF_B;      // [144][PA] ent tile (raw f32)
    float* sNH = sm + OFF_NH;     // [128]
    float* sNE = sm + OFF_NE;     // [144]

    const int tid  = threadIdx.x;
    const int lane = tid & 31;
    const int warp = tid >> 5;
    const int jT   = blockIdx.x * BN;
    const int iT   = blockIdx.y * BM;

    // ---- load B tile (ent rows jT..jT+143) + ne ----
#pragma unroll
    for (int it = 0; it < 9; it++) {
        int idx = it * 256 + tid;       // 2304 float4 slots
        int row = idx >> 4;
        int q   = idx & 15;
        int jG  = jT + row;
        float4 v = make_float4(0.f, 0.f, 0.f, 0.f);
        if (jG < ENT) v = *(const float4*)(ent + (size_t)jG * DIM + q * 4);
        float s = v.x * v.x + v.y * v.y + v.z * v.z + v.w * v.w;
#pragma unroll
        for (int o = 8; o >= 1; o >>= 1) s += __shfl_xor_sync(0xffffffffu, s, o, 16);
        if (q == 0) sNE[row] = s;
        *(float4*)(sB + row * PA + q * 4) = v;
    }
    // ---- load A tile: hr = ent[h]+rel[r], rows iT..iT+127, + nh ----
#pragma unroll
    for (int it = 0; it < 8; it++) {
        int idx = it * 256 + tid;       // 2048 float4 slots
        int row = idx >> 4;
        int q   = idx & 15;
        int hI  = h[iT + row];
        int rI  = r[iT + row];
        float4 a = *(const float4*)(ent + (size_t)hI * DIM + q * 4);
        float4 c = *(const float4*)(rel + (size_t)rI * DIM + q * 4);
        float4 v = make_float4(a.x + c.x, a.y + c.y, a.z + c.z, a.w + c.w);
        float s = v.x * v.x + v.y * v.y + v.z * v.z + v.w * v.w;
#pragma unroll
        for (int o = 8; o >= 1; o >>= 1) s += __shfl_xor_sync(0xffffffffu, s, o, 16);
        if (q == 0) sNH[row] = s;
        *(float4*)(sA + row * PA + q * 4) = v;
    }
    __syncthreads();

    // ---- mainloop: warp (wm, wn); warp tile 32 x 72 ----
    const int wm  = warp >> 1;      // 0..3
    const int wn  = warp & 1;       // 0..1
    const int grp = lane >> 2;      // 0..7
    const int t4  = lane & 3;       // 0..3

    const uint32_t* uA = (const uint32_t*)sA;
    const uint32_t* uB = (const uint32_t*)sB;
    const int aR = (wm * 32 + grp) * PA;
    const int bR = (wn * 72 + grp) * PA;

    float d[2][9][4];
#pragma unroll
    for (int f = 0; f < 2; f++)
#pragma unroll
        for (int g = 0; g < 9; g++)
#pragma unroll
            for (int e = 0; e < 4; e++) d[f][g][e] = 0.0f;

#pragma unroll
    for (int ch = 0; ch < 8; ch++) {
        const int kb = ch * 8 + t4;
        uint32_t a[2][4];
#pragma unroll
        for (int f = 0; f < 2; f++) {
            int base = aR + f * 16 * PA;
            a[f][0] = uA[base + kb];
            a[f][1] = uA[base + 8 * PA + kb];
            a[f][2] = uA[base + kb + 4];
            a[f][3] = uA[base + 8 * PA + kb + 4];
        }
#pragma unroll
        for (int g = 0; g < 9; g++) {
            uint32_t b0 = uB[bR + g * 8 * PA + kb];
            uint32_t b1 = uB[bR + g * 8 * PA + kb + 4];
            mma_tf32(d[0][g], a[0], b0, b1);
            mma_tf32(d[1][g], a[1], b0, b1);
        }
    }

    // ---- epilogue: c0/c1 at (row, 2*t4 / +1); c2/c3 at row+8 ----
#pragma unroll
    for (int f = 0; f < 2; f++) {
        int rl0 = wm * 32 + f * 16 + grp;
        int rl1 = rl0 + 8;
        float nh0 = sNH[rl0];
        float nh1 = sNH[rl1];
        float* o0 = out + (size_t)(iT + rl0) * ENT + jT;
        float* o1 = out + (size_t)(iT + rl1) * ENT + jT;
#pragma unroll
        for (int g = 0; g < 9; g++) {
            int cl = wn * 72 + g * 8 + t4 * 2;
            if (jT + cl < ENT) {
                float2 ne2 = *(const float2*)(sNE + cl);
                float2 s0, s1;
                s0.x = sqrt_approx(fmaxf(nh0 + ne2.x - 2.0f * d[f][g][0], 0.0f));
                s0.y = sqrt_approx(fmaxf(nh0 + ne2.y - 2.0f * d[f][g][1], 0.0f));
                s1.x = sqrt_approx(fmaxf(nh1 + ne2.x - 2.0f * d[f][g][2], 0.0f));
                s1.y = sqrt_approx(fmaxf(nh1 + ne2.y - 2.0f * d[f][g][3], 0.0f));
                *(float2*)(o0 + cl) = s0;
                *(float2*)(o1 + cl) = s1;
            }
        }
    }
}

// ---------------------------------------------------------------------------
// Inputs (metadata order): ent_emb f32[20000*64], rel_emb f32[500*64],
//                          h i32[256], r i32[256], t i32[256], (batch_size)
// Output: f32[256*20000]
// ---------------------------------------------------------------------------
extern "C" void kernel_launch(void* const* d_in, const int* in_sizes, int n_in,
                              void* d_out, int out_size) {
    const float* ent = (const float*)d_in[0];
    const float* rel = (const float*)d_in[1];
    const int*   h   = (const int*)d_in[2];
    const int*   r   = (const int*)d_in[3];
    float*       out = (float*)d_out;

    cudaFuncSetAttribute(transe_mma_kernel,
                         cudaFuncAttributeMaxDynamicSharedMemorySize, SM_BYTES);

    dim3 grid(NCT, TSZ / BM);       // 139 x 2 = 278 CTAs, one tile each
    transe_mma_kernel<<<grid, 256, SM_BYTES>>>(ent, rel, h, r, out);
}

// round 10
// speedup vs baseline: 3.1375x; 1.0089x over previous
#include <cuda_runtime.h>
#include <cstdint>
#include <math.h>

#define ENT   20000
#define RELN  500
#define DIM   64
#define TSZ   256
#define BM    128
#define BN    96          // 12 n8-tiles; 209 col tiles cover 20064 >= 20000
#define NCT   209
#define PA    68          // smem pitch in floats (bank-bijective fragments)

// SMEM float offsets
#define OFF_A   0
#define OFF_B   (BM * PA)                  // 8704
#define OFF_NH  (OFF_B + BN * PA)          // 15232
#define OFF_NE  (OFF_NH + BM)              // 15360
#define SM_FLOATS (OFF_NE + BN)            // 15456
#define SM_BYTES  (SM_FLOATS * 4)          // 61824

__device__ __forceinline__ float sqrt_approx(float x) {
    float y;
    asm("sqrt.approx.f32 %0, %1;" : "=f"(y) : "f"(x));
    return y;
}
__device__ __forceinline__ void mma_tf32(float* d, const uint32_t* a,
                                         uint32_t b0, uint32_t b1) {
    asm volatile(
        "mma.sync.aligned.m16n8k8.row.col.f32.tf32.tf32.f32 "
        "{%0,%1,%2,%3}, {%4,%5,%6,%7}, {%8,%9}, {%0,%1,%2,%3};"
        : "+f"(d[0]), "+f"(d[1]), "+f"(d[2]), "+f"(d[3])
        : "r"(a[0]), "r"(a[1]), "r"(a[2]), "r"(a[3]), "r"(b0), "r"(b1));
}

// ---------------------------------------------------------------------------
// score[i][j] = sqrt(||hr_i||^2 + ||ent_j||^2 - 2 * dot(hr_i, ent_j))
// Tile 128 x 96 per CTA; 418 CTAs, 3 resident per SM (reg-capped 84).
// tf32 MMA on raw f32 bits (HW truncation); norms fused into tile loads.
// ---------------------------------------------------------------------------
__global__ void __launch_bounds__(256, 3)
transe_mma_kernel(const float* __restrict__ ent, const float* __restrict__ rel,
                  const int* __restrict__ h, const int* __restrict__ r,
                  float* __restrict__ out) {
    extern __shared__ float sm[];
    float* sA  = sm + OFF_A;      // [128][PA] hr (raw f32)
    float* sB  = sm + OFF_B;      // [96][PA] ent tile (raw f32)
    float* sNH = sm + OFF_NH;     // [128]
    float* sNE = sm + OFF_NE;     // [96]

    const int tid  = threadIdx.x;
    const int lane = tid & 31;
    const int warp = tid >> 5;
    const int jT   = blockIdx.x * BN;
    const int iT   = blockIdx.y * BM;

    // ---- load B tile (ent rows jT..jT+95) + ne ----
#pragma unroll
    for (int it = 0; it < 6; it++) {
        int idx = it * 256 + tid;       // 1536 float4 slots
        int row = idx >> 4;
        int q   = idx & 15;
        int jG  = jT + row;
        float4 v = make_float4(0.f, 0.f, 0.f, 0.f);
        if (jG < ENT) v = *(const float4*)(ent + (size_t)jG * DIM + q * 4);
        float s = v.x * v.x + v.y * v.y + v.z * v.z + v.w * v.w;
#pragma unroll
        for (int o = 8; o >= 1; o >>= 1) s += __shfl_xor_sync(0xffffffffu, s, o, 16);
        if (q == 0) sNE[row] = s;
        *(float4*)(sB + row * PA + q * 4) = v;
    }
    // ---- load A tile: hr = ent[h]+rel[r], rows iT..iT+127, + nh ----
#pragma unroll
    for (int it = 0; it < 8; it++) {
        int idx = it * 256 + tid;       // 2048 float4 slots
        int row = idx >> 4;
        int q   = idx & 15;
        int hI  = h[iT + row];
        int rI  = r[iT + row];
        float4 a = *(const float4*)(ent + (size_t)hI * DIM + q * 4);
        float4 c = *(const float4*)(rel + (size_t)rI * DIM + q * 4);
        float4 v = make_float4(a.x + c.x, a.y + c.y, a.z + c.z, a.w + c.w);
        float s = v.x * v.x + v.y * v.y + v.z * v.z + v.w * v.w;
#pragma unroll
        for (int o = 8; o >= 1; o >>= 1) s += __shfl_xor_sync(0xffffffffu, s, o, 16);
        if (q == 0) sNH[row] = s;
        *(float4*)(sA + row * PA + q * 4) = v;
    }
    __syncthreads();

    // ---- mainloop: warp (wm, wn); warp tile 32 x 48 ----
    const int wm  = warp >> 1;      // 0..3
    const int wn  = warp & 1;       // 0..1
    const int grp = lane >> 2;      // 0..7
    const int t4  = lane & 3;       // 0..3

    const uint32_t* uA = (const uint32_t*)sA;
    const uint32_t* uB = (const uint32_t*)sB;
    const int aR = (wm * 32 + grp) * PA;
    const int bR = (wn * 48 + grp) * PA;

    float d[2][6][4];
#pragma unroll
    for (int f = 0; f < 2; f++)
#pragma unroll
        for (int g = 0; g < 6; g++)
#pragma unroll
            for (int e = 0; e < 4; e++) d[f][g][e] = 0.0f;

#pragma unroll
    for (int ch = 0; ch < 8; ch++) {
        const int kb = ch * 8 + t4;
        uint32_t a[2][4];
#pragma unroll
        for (int f = 0; f < 2; f++) {
            int base = aR + f * 16 * PA;
            a[f][0] = uA[base + kb];
            a[f][1] = uA[base + 8 * PA + kb];
            a[f][2] = uA[base + kb + 4];
            a[f][3] = uA[base + 8 * PA + kb + 4];
        }
#pragma unroll
        for (int g = 0; g < 6; g++) {
            uint32_t b0 = uB[bR + g * 8 * PA + kb];
            uint32_t b1 = uB[bR + g * 8 * PA + kb + 4];
            mma_tf32(d[0][g], a[0], b0, b1);
            mma_tf32(d[1][g], a[1], b0, b1);
        }
    }

    // ---- epilogue: c0/c1 at (row, 2*t4 / +1); c2/c3 at row+8 ----
#pragma unroll
    for (int f = 0; f < 2; f++) {
        int rl0 = wm * 32 + f * 16 + grp;
        int rl1 = rl0 + 8;
        float nh0 = sNH[rl0];
        float nh1 = sNH[rl1];
        float* o0 = out + (size_t)(iT + rl0) * ENT + jT;
        float* o1 = out + (size_t)(iT + rl1) * ENT + jT;
#pragma unroll
        for (int g = 0; g < 6; g++) {
            int cl = wn * 48 + g * 8 + t4 * 2;
            if (jT + cl < ENT) {
                float2 ne2 = *(const float2*)(sNE + cl);
                float2 s0, s1;
                s0.x = sqrt_approx(fmaxf(nh0 + ne2.x - 2.0f * d[f][g][0], 0.0f));
                s0.y = sqrt_approx(fmaxf(nh0 + ne2.y - 2.0f * d[f][g][1], 0.0f));
                s1.x = sqrt_approx(fmaxf(nh1 + ne2.x - 2.0f * d[f][g][2], 0.0f));
                s1.y = sqrt_approx(fmaxf(nh1 + ne2.y - 2.0f * d[f][g][3], 0.0f));
                *(float2*)(o0 + cl) = s0;
                *(float2*)(o1 + cl) = s1;
            }
        }
    }
}

// ---------------------------------------------------------------------------
// Inputs (metadata order): ent_emb f32[20000*64], rel_emb f32[500*64],
//                          h i32[256], r i32[256], t i32[256], (batch_size)
// Output: f32[256*20000]
// ---------------------------------------------------------------------------
extern "C" void kernel_launch(void* const* d_in, const int* in_sizes, int n_in,
                              void* d_out, int out_size) {
    const float* ent = (const float*)d_in[0];
    const float* rel = (const float*)d_in[1];
    const int*   h   = (const int*)d_in[2];
    const int*   r   = (const int*)d_in[3];
    float*       out = (float*)d_out;

    cudaFuncSetAttribute(transe_mma_kernel,
                         cudaFuncAttributeMaxDynamicSharedMemorySize, SM_BYTES);

    dim3 grid(NCT, TSZ / BM);       // 209 x 2 = 418 CTAs, one tile each
    transe_mma_kernel<<<grid, 256, SM_BYTES>>>(ent, rel, h, r, out);
}

// round 12
// speedup vs baseline: 3.6189x; 1.1535x over previous
#include <cuda_runtime.h>
#include <cstdint>
#include <math.h>

#define ENT   20000
#define RELN  500
#define DIM   64
#define TSZ   256
#define BM    128
#define BN    96          // 12 n8-tiles; 209 col tiles cover 20064 >= 20000
#define NCT   209
#define PW    36          // smem pitch in 4B words (72 bf16); 36%32=4 -> bank-bijective

// SMEM word offsets
#define OFF_A   0                     // [128][PW] bf16x2 words of hr
#define OFF_B   (BM * PW)             // 4608: [96][PW] bf16x2 words of ent tile
#define OFF_NH  (OFF_B + BN * PW)     // 8064: [128] f32
#define OFF_NE  (OFF_NH + BM)         // 8192: [96] f32
#define SM_WORDS (OFF_NE + BN)        // 8288
#define SM_BYTES (SM_WORDS * 4)       // 33152

__device__ __forceinline__ float sqrt_approx(float x) {
    float y;
    asm("sqrt.approx.f32 %0, %1;" : "=f"(y) : "f"(x));
    return y;
}
// pack (lo=a, hi=b) as bf16x2
__device__ __forceinline__ uint32_t bf16x2(float lo, float hi) {
    uint32_t u;
    asm("cvt.rn.bf16x2.f32 %0, %1, %2;" : "=r"(u) : "f"(hi), "f"(lo));
    return u;
}
__device__ __forceinline__ void mma_bf16(float* d, const uint32_t* a,
                                         uint32_t b0, uint32_t b1) {
    asm volatile(
        "mma.sync.aligned.m16n8k16.row.col.f32.bf16.bf16.f32 "
        "{%0,%1,%2,%3}, {%4,%5,%6,%7}, {%8,%9}, {%0,%1,%2,%3};"
        : "+f"(d[0]), "+f"(d[1]), "+f"(d[2]), "+f"(d[3])
        : "r"(a[0]), "r"(a[1]), "r"(a[2]), "r"(a[3]), "r"(b0), "r"(b1));
}

// ---------------------------------------------------------------------------
// score[i][j] = sqrt(||hr_i||^2 + ||ent_j||^2 - 2 * dot(hr_i, ent_j))
// Cross term in bf16 MMA (m16n8k16, f32 accum); norms exact f32, fused in load.
// Tile 128 x 96 per CTA; 418 CTAs, 3 resident per SM.
// ---------------------------------------------------------------------------
__global__ void __launch_bounds__(256, 3)
transe_mma_kernel(const float* __restrict__ ent, const float* __restrict__ rel,
                  const int* __restrict__ h, const int* __restrict__ r,
                  float* __restrict__ out) {
    extern __shared__ uint32_t smw[];
    uint32_t* sA  = smw + OFF_A;
    uint32_t* sB  = smw + OFF_B;
    float*    sNH = (float*)(smw + OFF_NH);
    float*    sNE = (float*)(smw + OFF_NE);

    const int tid  = threadIdx.x;
    const int lane = tid & 31;
    const int warp = tid >> 5;
    const int jT   = blockIdx.x * BN;
    const int iT   = blockIdx.y * BM;

    // ---- load B tile (ent rows jT..jT+95): f32 norms + bf16x2 STS.64 ----
#pragma unroll
    for (int it = 0; it < 6; it++) {
        int idx = it * 256 + tid;       // 1536 float4 slots
        int row = idx >> 4;
        int q   = idx & 15;
        int jG  = jT + row;
        float4 v = make_float4(0.f, 0.f, 0.f, 0.f);
        if (jG < ENT) v = *(const float4*)(ent + (size_t)jG * DIM + q * 4);
        float s = v.x * v.x + v.y * v.y + v.z * v.z + v.w * v.w;
#pragma unroll
        for (int o = 8; o >= 1; o >>= 1) s += __shfl_xor_sync(0xffffffffu, s, o, 16);
        if (q == 0) sNE[row] = s;
        uint32_t* dst = sB + row * PW + q * 2;
        dst[0] = bf16x2(v.x, v.y);
        dst[1] = bf16x2(v.z, v.w);
    }
    // ---- load A tile: hr = ent[h]+rel[r], rows iT..iT+127 ----
#pragma unroll
    for (int it = 0; it < 8; it++) {
        int idx = it * 256 + tid;       // 2048 float4 slots
        int row = idx >> 4;
        int q   = idx & 15;
        int hI  = h[iT + row];
        int rI  = r[iT + row];
        float4 a = *(const float4*)(ent + (size_t)hI * DIM + q * 4);
        float4 c = *(const float4*)(rel + (size_t)rI * DIM + q * 4);
        float4 v = make_float4(a.x + c.x, a.y + c.y, a.z + c.z, a.w + c.w);
        float s = v.x * v.x + v.y * v.y + v.z * v.z + v.w * v.w;
#pragma unroll
        for (int o = 8; o >= 1; o >>= 1) s += __shfl_xor_sync(0xffffffffu, s, o, 16);
        if (q == 0) sNH[row] = s;
        uint32_t* dst = sA + row * PW + q * 2;
        dst[0] = bf16x2(v.x, v.y);
        dst[1] = bf16x2(v.z, v.w);
    }
    __syncthreads();

    // ---- mainloop: warp (wm, wn); warp tile 32 x 48; 4 k16 chunks ----
    const int wm  = warp >> 1;      // 0..3
    const int wn  = warp & 1;       // 0..1
    const int grp = lane >> 2;      // 0..7
    const int t4  = lane & 3;       // 0..3

    float d[2][6][4];
#pragma unroll
    for (int f = 0; f < 2; f++)
#pragma unroll
        for (int g = 0; g < 6; g++)
#pragma unroll
            for (int e = 0; e < 4; e++) d[f][g][e] = 0.0f;

#pragma unroll
    for (int ch = 0; ch < 4; ch++) {
        const int k0 = ch * 8 + t4;     // bf16x2-word index within row
        uint32_t a[2][4];
#pragma unroll
        for (int f = 0; f < 2; f++) {
            int base = (wm * 32 + f * 16 + grp) * PW;
            a[f][0] = sA[base + k0];
            a[f][1] = sA[base + 8 * PW + k0];
            a[f][2] = sA[base + k0 + 4];
            a[f][3] = sA[base + 8 * PW + k0 + 4];
        }
#pragma unroll
        for (int g = 0; g < 6; g++) {
            int bbase = (wn * 48 + g * 8 + grp) * PW;
            uint32_t b0 = sB[bbase + k0];
            uint32_t b1 = sB[bbase + k0 + 4];
            mma_bf16(d[0][g], a[0], b0, b1);
            mma_bf16(d[1][g], a[1], b0, b1);
        }
    }

    // ---- epilogue: c0/c1 at (row, 2*t4 / +1); c2/c3 at row+8 ----
#pragma unroll
    for (int f = 0; f < 2; f++) {
        int rl0 = wm * 32 + f * 16 + grp;
        int rl1 = rl0 + 8;
        float nh0 = sNH[rl0];
        float nh1 = sNH[rl1];
        float* o0 = out + (size_t)(iT + rl0) * ENT + jT;
        float* o1 = out + (size_t)(iT + rl1) * ENT + jT;
#pragma unroll
        for (int g = 0; g < 6; g++) {
            int cl = wn * 48 + g * 8 + t4 * 2;
            if (jT + cl < ENT) {
                float2 ne2 = *(const float2*)(sNE + cl);
                float2 s0, s1;
                s0.x = sqrt_approx(fmaxf(nh0 + ne2.x - 2.0f * d[f][g][0], 0.0f));
                s0.y = sqrt_approx(fmaxf(nh0 + ne2.y - 2.0f * d[f][g][1], 0.0f));
                s1.x = sqrt_approx(fmaxf(nh1 + ne2.x - 2.0f * d[f][g][2], 0.0f));
                s1.y = sqrt_approx(fmaxf(nh1 + ne2.y - 2.0f * d[f][g][3], 0.0f));
                *(float2*)(o0 + cl) = s0;
                *(float2*)(o1 + cl) = s1;
            }
        }
    }
}

// ---------------------------------------------------------------------------
// Inputs (metadata order): ent_emb f32[20000*64], rel_emb f32[500*64],
//                          h i32[256], r i32[256], t i32[256], (batch_size)
// Output: f32[256*20000]
// ---------------------------------------------------------------------------
extern "C" void kernel_launch(void* const* d_in, const int* in_sizes, int n_in,
                              void* d_out, int out_size) {
    const float* ent = (const float*)d_in[0];
    const float* rel = (const float*)d_in[1];
    const int*   h   = (const int*)d_in[2];
    const int*   r   = (const int*)d_in[3];
    float*       out = (float*)d_out;

    cudaFuncSetAttribute(transe_mma_kernel,
                         cudaFuncAttributeMaxDynamicSharedMemorySize, SM_BYTES);

    dim3 grid(NCT, TSZ / BM);       // 209 x 2 = 418 CTAs, one tile each
    transe_mma_kernel<<<grid, 256, SM_BYTES>>>(ent, rel, h, r, out);
}